// round 1
// baseline (speedup 1.0000x reference)
#include <cuda_runtime.h>

// ---------------------------------------------------------------------------
// Generator3DLUT: out[b,c,h,w] = trilinear(LUT[c], x[b,:,h,w])
//   x:   (8, 3, 1024, 1024) fp32
//   LUT: (3, 33, 33, 33)    fp32   (channel-major, k innermost)
// t = clamp(x * (D-1), 0, D-1); 8-corner trilinear gather per pixel.
// ---------------------------------------------------------------------------

#define LUT_D   33
#define LUT_D3  (33 * 33 * 33)      // 35937
#define IMG_HW  (1024 * 1024)
#define IMG_HW4 (IMG_HW / 4)        // 262144 = 2^18
#define BATCH   8

// Interleaved LUT: one float4 per lattice point = (c0, c1, c2, pad).
// 575 KB -> L2-resident. Turns 3 scattered scalar gathers into one LDG.128.
__device__ float4 g_lutI[LUT_D3];

__global__ void lut_interleave_kernel(const float* __restrict__ lut) {
    int i = blockIdx.x * blockDim.x + threadIdx.x;
    if (i < LUT_D3) {
        g_lutI[i] = make_float4(lut[i],
                                lut[LUT_D3 + i],
                                lut[2 * LUT_D3 + i],
                                0.0f);
    }
}

__device__ __forceinline__ float3 lut_fetch(int idx) {
    float4 v = __ldg(reinterpret_cast<const float4*>(g_lutI) + idx);
    return make_float3(v.x, v.y, v.z);
}

__device__ __forceinline__ float3 lerp3(float3 a, float3 b, float w) {
    return make_float3(fmaf(w, b.x - a.x, a.x),
                       fmaf(w, b.y - a.y, a.y),
                       fmaf(w, b.z - a.z, a.z));
}

// Trilinear lookup for one pixel. r -> k axis, g -> j axis, b -> i axis.
__device__ __forceinline__ float3 trilerp(float r, float g, float bl) {
    float tr = fminf(fmaxf(r  * 32.0f, 0.0f), 32.0f);
    float tg = fminf(fmaxf(g  * 32.0f, 0.0f), 32.0f);
    float tb = fminf(fmaxf(bl * 32.0f, 0.0f), 32.0f);

    float kf = floorf(tr); float wk = tr - kf;
    float jf = floorf(tg); float wj = tg - jf;
    float iff = floorf(tb); float wi = tb - iff;

    int k0 = (int)kf; int k1 = min(k0 + 1, LUT_D - 1);
    int j0 = (int)jf; int j1 = min(j0 + 1, LUT_D - 1);
    int i0 = (int)iff; int i1 = min(i0 + 1, LUT_D - 1);

    int b00 = (i0 * LUT_D + j0) * LUT_D;
    int b01 = (i0 * LUT_D + j1) * LUT_D;
    int b10 = (i1 * LUT_D + j0) * LUT_D;
    int b11 = (i1 * LUT_D + j1) * LUT_D;

    float3 c000 = lut_fetch(b00 + k0);
    float3 c001 = lut_fetch(b00 + k1);
    float3 c010 = lut_fetch(b01 + k0);
    float3 c011 = lut_fetch(b01 + k1);
    float3 c100 = lut_fetch(b10 + k0);
    float3 c101 = lut_fetch(b10 + k1);
    float3 c110 = lut_fetch(b11 + k0);
    float3 c111 = lut_fetch(b11 + k1);

    float3 c00 = lerp3(c000, c001, wk);
    float3 c01 = lerp3(c010, c011, wk);
    float3 c10 = lerp3(c100, c101, wk);
    float3 c11 = lerp3(c110, c111, wk);

    float3 c0 = lerp3(c00, c01, wj);
    float3 c1 = lerp3(c10, c11, wj);
    return lerp3(c0, c1, wi);
}

__global__ void __launch_bounds__(256)
lut_apply_kernel(const float4* __restrict__ x,
                 float4* __restrict__ out) {
    int t = blockIdx.x * blockDim.x + threadIdx.x;
    // total threads = BATCH * IMG_HW4; grid sized exactly, no bounds check needed
    int b   = t >> 18;               // t / IMG_HW4
    int off = t & (IMG_HW4 - 1);     // t % IMG_HW4

    const float4* in_base = x + (size_t)b * 3 * IMG_HW4;
    float4 r4 = in_base[off];
    float4 g4 = in_base[off + IMG_HW4];
    float4 b4 = in_base[off + 2 * IMG_HW4];

    const float* rp = reinterpret_cast<const float*>(&r4);
    const float* gp = reinterpret_cast<const float*>(&g4);
    const float* bp = reinterpret_cast<const float*>(&b4);

    float4 o0, o1, o2;
    float* o0p = reinterpret_cast<float*>(&o0);
    float* o1p = reinterpret_cast<float*>(&o1);
    float* o2p = reinterpret_cast<float*>(&o2);

#pragma unroll
    for (int l = 0; l < 4; ++l) {
        float3 c = trilerp(rp[l], gp[l], bp[l]);
        o0p[l] = c.x;
        o1p[l] = c.y;
        o2p[l] = c.z;
    }

    float4* out_base = out + (size_t)b * 3 * IMG_HW4;
    out_base[off]               = o0;
    out_base[off + IMG_HW4]     = o1;
    out_base[off + 2 * IMG_HW4] = o2;
}

extern "C" void kernel_launch(void* const* d_in, const int* in_sizes, int n_in,
                              void* d_out, int out_size) {
    const float* x   = (const float*)d_in[0];
    const float* lut = (const float*)d_in[1];
    // Defensive: metadata order should be (x, LUT); swap if sizes say otherwise.
    if (n_in >= 2 && in_sizes[0] == 3 * LUT_D3) {
        const float* tmp = x; x = lut; lut = tmp;
    }

    lut_interleave_kernel<<<(LUT_D3 + 255) / 256, 256>>>(lut);

    int total4 = BATCH * IMG_HW4;   // 2,097,152 threads
    lut_apply_kernel<<<total4 / 256, 256>>>(
        reinterpret_cast<const float4*>(x),
        reinterpret_cast<float4*>(d_out));
}

// round 2
// speedup vs baseline: 2.4931x; 2.4931x over previous
#include <cuda_runtime.h>
#include <cuda_fp16.h>

// ---------------------------------------------------------------------------
// Generator3DLUT: out[b,c,h,w] = trilinear(LUT[c], x[b,:,h,w])
//   x:   (8, 3, 1024, 1024) fp32
//   LUT: (3, 33, 33, 33)    fp32 (channel-major, k innermost)
//
// R2 strategy: the R1 profile showed L1tex=94.5% (random LDG gathers) with
// DRAM at 10.9%. Move the LUT into shared memory as fp16:
//   half2 ab[35937] (c0,c1)  = 143,748 B
//   half  c2[35937]          =  71,874 B   -> total 215,622 B < 227 KB/CTA
// Each corner gather = LDS.32 + LDS.U16 instead of a random LDG.128.
// fp16 storage keeps elementwise relative error <= 2^-11 ~ 4.9e-4 < 1e-3.
// ---------------------------------------------------------------------------

#define LUT_D    33
#define LUT_D3   35937          // 33^3
#define IMG_HW4  262144         // 1024*1024/4
#define BATCH    8
#define TOTAL4   (BATCH * IMG_HW4)   // 2,097,152 float4-groups

#define SMEM_AB_BYTES (LUT_D3 * 4)             // 143748
#define SMEM_C_BYTES  (LUT_D3 * 2)             // 71874
#define SMEM_TOTAL    (SMEM_AB_BYTES + SMEM_C_BYTES)  // 215622

struct Corner { float x, y, z; };

__device__ __forceinline__ Corner fetch_corner(const __half2* __restrict__ ab,
                                               const __half*  __restrict__ c2,
                                               int idx) {
    float2 f = __half22float2(ab[idx]);
    Corner r;
    r.x = f.x;
    r.y = f.y;
    r.z = __half2float(c2[idx]);
    return r;
}

__device__ __forceinline__ Corner lerpC(Corner a, Corner b, float w) {
    Corner r;
    r.x = fmaf(w, b.x - a.x, a.x);
    r.y = fmaf(w, b.y - a.y, a.y);
    r.z = fmaf(w, b.z - a.z, a.z);
    return r;
}

// Trilinear lookup for one pixel. r -> k axis, g -> j axis, b -> i axis.
__device__ __forceinline__ Corner trilerp(const __half2* __restrict__ ab,
                                          const __half*  __restrict__ c2,
                                          float r, float g, float bl) {
    float tr = fminf(fmaxf(r  * 32.0f, 0.0f), 32.0f);
    float tg = fminf(fmaxf(g  * 32.0f, 0.0f), 32.0f);
    float tb = fminf(fmaxf(bl * 32.0f, 0.0f), 32.0f);

    float kf = floorf(tr); float wk = tr - kf;
    float jf = floorf(tg); float wj = tg - jf;
    float iff = floorf(tb); float wi = tb - iff;

    int k0 = (int)kf; int k1 = min(k0 + 1, LUT_D - 1);
    int j0 = (int)jf; int j1 = min(j0 + 1, LUT_D - 1);
    int i0 = (int)iff; int i1 = min(i0 + 1, LUT_D - 1);

    int b00 = (i0 * LUT_D + j0) * LUT_D;
    int b01 = (i0 * LUT_D + j1) * LUT_D;
    int b10 = (i1 * LUT_D + j0) * LUT_D;
    int b11 = (i1 * LUT_D + j1) * LUT_D;

    Corner c000 = fetch_corner(ab, c2, b00 + k0);
    Corner c001 = fetch_corner(ab, c2, b00 + k1);
    Corner c010 = fetch_corner(ab, c2, b01 + k0);
    Corner c011 = fetch_corner(ab, c2, b01 + k1);
    Corner c100 = fetch_corner(ab, c2, b10 + k0);
    Corner c101 = fetch_corner(ab, c2, b10 + k1);
    Corner c110 = fetch_corner(ab, c2, b11 + k0);
    Corner c111 = fetch_corner(ab, c2, b11 + k1);

    Corner c00 = lerpC(c000, c001, wk);
    Corner c01 = lerpC(c010, c011, wk);
    Corner c10 = lerpC(c100, c101, wk);
    Corner c11 = lerpC(c110, c111, wk);

    Corner c0 = lerpC(c00, c01, wj);
    Corner c1 = lerpC(c10, c11, wj);
    return lerpC(c0, c1, wi);
}

extern __shared__ char s_raw[];

__global__ void __launch_bounds__(1024, 1)
lut_apply_smem_kernel(const float4* __restrict__ x,
                      const float*  __restrict__ lut,
                      float4* __restrict__ out) {
    __half2* s_ab = reinterpret_cast<__half2*>(s_raw);
    __half*  s_c2 = reinterpret_cast<__half*>(s_raw + SMEM_AB_BYTES);

    // Fill smem LUT: fp32 -> fp16 convert. ~36 iters/thread, L2-served.
    for (int i = threadIdx.x; i < LUT_D3; i += blockDim.x) {
        float a = lut[i];
        float b = lut[LUT_D3 + i];
        float c = lut[2 * LUT_D3 + i];
        s_ab[i] = __floats2half2_rn(a, b);
        s_c2[i] = __float2half_rn(c);
    }
    __syncthreads();

    const int stride = gridDim.x * blockDim.x;
    for (int t = blockIdx.x * blockDim.x + threadIdx.x; t < TOTAL4; t += stride) {
        int b   = t >> 18;              // t / IMG_HW4
        int off = t & (IMG_HW4 - 1);    // t % IMG_HW4

        const float4* in_base = x + (size_t)b * 3 * IMG_HW4;
        float4 r4 = in_base[off];
        float4 g4 = in_base[off + IMG_HW4];
        float4 b4 = in_base[off + 2 * IMG_HW4];

        const float* rp = reinterpret_cast<const float*>(&r4);
        const float* gp = reinterpret_cast<const float*>(&g4);
        const float* bp = reinterpret_cast<const float*>(&b4);

        float4 o0, o1, o2;
        float* o0p = reinterpret_cast<float*>(&o0);
        float* o1p = reinterpret_cast<float*>(&o1);
        float* o2p = reinterpret_cast<float*>(&o2);

#pragma unroll
        for (int l = 0; l < 4; ++l) {
            Corner c = trilerp(s_ab, s_c2, rp[l], gp[l], bp[l]);
            o0p[l] = c.x;
            o1p[l] = c.y;
            o2p[l] = c.z;
        }

        float4* out_base = out + (size_t)b * 3 * IMG_HW4;
        out_base[off]               = o0;
        out_base[off + IMG_HW4]     = o1;
        out_base[off + 2 * IMG_HW4] = o2;
    }
}

extern "C" void kernel_launch(void* const* d_in, const int* in_sizes, int n_in,
                              void* d_out, int out_size) {
    const float* x   = (const float*)d_in[0];
    const float* lut = (const float*)d_in[1];
    // Defensive: metadata order should be (x, LUT); swap if sizes say otherwise.
    if (n_in >= 2 && in_sizes[0] == 3 * LUT_D3) {
        const float* tmp = x; x = lut; lut = tmp;
    }

    static int nsm = []() {
        cudaDeviceProp p;
        cudaGetDeviceProperties(&p, 0);
        return p.multiProcessorCount;
    }();

    static bool attr_done = []() {
        cudaFuncSetAttribute(lut_apply_smem_kernel,
                             cudaFuncAttributeMaxDynamicSharedMemorySize,
                             SMEM_TOTAL);
        return true;
    }();
    (void)attr_done;

    lut_apply_smem_kernel<<<nsm, 1024, SMEM_TOTAL>>>(
        reinterpret_cast<const float4*>(x),
        lut,
        reinterpret_cast<float4*>(d_out));
}